// round 1
// baseline (speedup 1.0000x reference)
#include <cuda_runtime.h>

#define NB 32
#define NIMG 640          // 32*5*4 images per backbone
#define CH 50176          // 224*224
#define IMG_SZ 150528     // 3*224*224

// scratch for backbone outputs: [2][640][6]
__device__ float g_backbone[2 * NIMG * 6];

// ---------------------------------------------------------------------------
// Backbone: conv(3->3,3x3,s2) -> maxpool(3,3) -> relu -> conv(3->1,3x3,s2)
//           -> maxpool(3,3) -> relu -> linear 36->6
// One block per (image, backbone). 224x224 streamed in 37 strips of 7 rows.
// ---------------------------------------------------------------------------
__global__ __launch_bounds__(256)
void backbone_kernel(const float* __restrict__ nodes,
                     const float* __restrict__ depths,
                     const float* __restrict__ c1w,  const float* __restrict__ c1b,
                     const float* __restrict__ c2w,  const float* __restrict__ c2b,
                     const float* __restrict__ lw,   const float* __restrict__ lb,
                     const float* __restrict__ dc1w, const float* __restrict__ dc1b,
                     const float* __restrict__ dc2w, const float* __restrict__ dc2b,
                     const float* __restrict__ dlw,  const float* __restrict__ dlb)
{
    const int img = blockIdx.x;   // 0..639
    const int bb  = blockIdx.y;   // 0 = rgb, 1 = depth
    const int tid = threadIdx.x;

    const float* in  = (bb == 0 ? nodes : depths) + (size_t)img * IMG_SZ;
    const float* w1  = bb == 0 ? c1w : dc1w;
    const float* b1  = bb == 0 ? c1b : dc1b;
    const float* w2  = bb == 0 ? c2w : dc2w;
    const float* b2  = bb == 0 ? c2b : dc2b;
    const float* lwp = bb == 0 ? lw  : dlw;
    const float* lbp = bb == 0 ? lb  : dlb;

    __shared__ float s_in[3][7][224];       // current input strip
    __shared__ float s_conv[3][3][112];     // conv1 rows (3 oc x 3 rows x 111)
    __shared__ float s_pool1[3][37][37];    // relu(pool1) result (stage-2 input)
    __shared__ float s_conv2[18][18];
    __shared__ float s_pool2[36];
    __shared__ float s_w1[81];
    __shared__ float s_b1[3];
    __shared__ float s_w2[27];
    __shared__ float s_b2[1];
    __shared__ float s_lw[216];
    __shared__ float s_lb[6];

    if (tid < 81)  s_w1[tid] = w1[tid];
    if (tid < 3)   s_b1[tid] = b1[tid];
    if (tid < 27)  s_w2[tid] = w2[tid];
    if (tid == 0)  s_b2[0]   = b2[0];
    if (tid < 216) s_lw[tid] = lwp[tid];
    if (tid < 6)   s_lb[tid] = lbp[tid];

    // ---- stage 1: 37 strips -------------------------------------------------
    for (int pr = 0; pr < 37; pr++) {
        // load input rows [6*pr, 6*pr+7) for all 3 channels, float4 coalesced
        const float* src = in + 6 * pr * 224;
        for (int q = tid; q < 3 * 7 * 56; q += 256) {
            int c  = q / 392;          // 7*56
            int rr = (q / 56) % 7;
            int x4 = q % 56;
            float4 v = *reinterpret_cast<const float4*>(src + c * CH + rr * 224 + x4 * 4);
            *reinterpret_cast<float4*>(&s_in[c][rr][x4 * 4]) = v;
        }
        __syncthreads();   // S1: s_in ready; also orders pool(prev) before conv

        // conv1: 3 oc x 111 cols, each thread-task computes 3 conv rows
        for (int t2 = tid; t2 < 333; t2 += 256) {
            int oc = t2 / 111;
            int x  = t2 % 111;
            float a0 = 0.f, a1 = 0.f, a2 = 0.f;
            #pragma unroll
            for (int ic = 0; ic < 3; ic++) {
                #pragma unroll
                for (int ky = 0; ky < 3; ky++) {
                    #pragma unroll
                    for (int kx = 0; kx < 3; kx++) {
                        float w = s_w1[(oc * 3 + ic) * 9 + ky * 3 + kx];
                        a0 += w * s_in[ic][ky    ][2 * x + kx];
                        a1 += w * s_in[ic][ky + 2][2 * x + kx];
                        a2 += w * s_in[ic][ky + 4][2 * x + kx];
                    }
                }
            }
            s_conv[oc][0][x] = a0;
            s_conv[oc][1][x] = a1;
            s_conv[oc][2][x] = a2;
        }
        __syncthreads();   // S2: s_conv ready; also orders conv before next load

        // pool1 + bias + relu: 3 oc x 37 cols
        if (tid < 111) {
            int oc = tid / 37, px = tid % 37;
            float m = -1e30f;
            #pragma unroll
            for (int j = 0; j < 3; j++)
                #pragma unroll
                for (int i = 0; i < 3; i++)
                    m = fmaxf(m, s_conv[oc][j][3 * px + i]);
            s_pool1[oc][pr][px] = fmaxf(m + s_b1[oc], 0.f);
        }
    }
    __syncthreads();

    // ---- stage 2: conv2 (18x18) ---------------------------------------------
    for (int t2 = tid; t2 < 324; t2 += 256) {
        int cy = t2 / 18, cx = t2 % 18;
        float acc = 0.f;
        #pragma unroll
        for (int ic = 0; ic < 3; ic++)
            #pragma unroll
            for (int ky = 0; ky < 3; ky++)
                #pragma unroll
                for (int kx = 0; kx < 3; kx++)
                    acc += s_w2[(ic * 3 + ky) * 3 + kx] *
                           s_pool1[ic][2 * cy + ky][2 * cx + kx];
        s_conv2[cy][cx] = acc;
    }
    __syncthreads();

    // pool2 + bias + relu -> 36 features
    if (tid < 36) {
        int py = tid / 6, px = tid % 6;
        float m = -1e30f;
        #pragma unroll
        for (int i = 0; i < 3; i++)
            #pragma unroll
            for (int j = 0; j < 3; j++)
                m = fmaxf(m, s_conv2[3 * py + i][3 * px + j]);
        s_pool2[tid] = fmaxf(m + s_b2[0], 0.f);
    }
    __syncthreads();

    // linear 36 -> 6
    if (tid < 6) {
        float acc = s_lb[tid];
        #pragma unroll
        for (int i = 0; i < 36; i++)
            acc += s_pool2[i] * s_lw[i * 6 + tid];
        g_backbone[bb * (NIMG * 6) + img * 6 + tid] = acc;
    }
}

// ---------------------------------------------------------------------------
// Head: message passing + concat + MLP 360->180->60->6. One block per sample.
// ---------------------------------------------------------------------------
__global__ __launch_bounds__(192)
void head_kernel(const float* __restrict__ pos,  const float* __restrict__ attmap,
                 const float* __restrict__ fmw,  const float* __restrict__ fmb,
                 const float* __restrict__ lmw,  const float* __restrict__ lmb,
                 const float* __restrict__ o1w,  const float* __restrict__ o1b,
                 const float* __restrict__ o2w,  const float* __restrict__ o2b,
                 const float* __restrict__ o3w,  const float* __restrict__ o3b,
                 float* __restrict__ out)
{
    const int b = blockIdx.x;
    const int t = threadIdx.x;

    __shared__ float feat[360];
    __shared__ float h1[180];
    __shared__ float h2[60];
    __shared__ float s_fmw[36], s_fmb[6], s_lmw[36], s_lmb[6];

    if (t < 36) { s_fmw[t] = fmw[t]; s_lmw[t] = lmw[t]; }
    if (t < 6)  { s_fmb[t] = fmb[t]; s_lmb[t] = lmb[t]; }

    // copy backbone features into concat layout [f*4+m][18] = {nf, df, pos_up}
    if (t < 120) {
        int f = t / 24, m = (t % 24) / 6, d = t % 6;
        int fm = f * 4 + m;
        int gi = ((b * 5 + f) * 4 + m) * 6 + d;
        feat[fm * 18 + d]     = g_backbone[gi];
        feat[fm * 18 + 6 + d] = g_backbone[NIMG * 6 + gi];
    }
    __syncthreads();

    // pos_up[b,f,n,d] = sum_m att[b,f,m,n]*(pos[b,f,m]@fmw + fmb)[d]
    //                 + (f>=1 ? (pos[b,f-1,n]@lmw + lmb)[d] : 0)
    if (t < 120) {
        int f = t / 24, n = (t % 24) / 6, d = t % 6;
        const float* pb = pos    + b * 120;  // [5][4][6]
        const float* ab = attmap + b * 80;   // [5][4][4]
        float acc = 0.f;
        #pragma unroll
        for (int m = 0; m < 4; m++) {
            float pm = s_fmb[d];
            #pragma unroll
            for (int e = 0; e < 6; e++)
                pm += pb[f * 24 + m * 6 + e] * s_fmw[e * 6 + d];
            acc += ab[f * 16 + m * 4 + n] * pm;
        }
        if (f >= 1) {
            float pv = s_lmb[d];
            #pragma unroll
            for (int e = 0; e < 6; e++)
                pv += pb[(f - 1) * 24 + n * 6 + e] * s_lmw[e * 6 + d];
            acc += pv;
        }
        feat[(f * 4 + n) * 18 + 12 + d] = acc;
    }
    __syncthreads();

    if (t < 180) {
        float a = o1b[t];
        for (int i = 0; i < 360; i++) a += feat[i] * o1w[i * 180 + t];
        h1[t] = fmaxf(a, 0.f);
    }
    __syncthreads();

    if (t < 60) {
        float a = o2b[t];
        for (int i = 0; i < 180; i++) a += h1[i] * o2w[i * 60 + t];
        h2[t] = fmaxf(a, 0.f);
    }
    __syncthreads();

    if (t < 6) {
        float a = o3b[t];
        for (int i = 0; i < 60; i++) a += h2[i] * o3w[i * 6 + t];
        out[b * 6 + t] = a;
    }
}

extern "C" void kernel_launch(void* const* d_in, const int* in_sizes, int n_in,
                              void* d_out, int out_size)
{
    const float* nodes  = (const float*)d_in[0];
    const float* pos    = (const float*)d_in[1];
    const float* attmap = (const float*)d_in[2];
    const float* depths = (const float*)d_in[3];
    const float* c1w  = (const float*)d_in[4];
    const float* c1b  = (const float*)d_in[5];
    const float* c2w  = (const float*)d_in[6];
    const float* c2b  = (const float*)d_in[7];
    const float* lw   = (const float*)d_in[8];
    const float* lb   = (const float*)d_in[9];
    const float* dc1w = (const float*)d_in[10];
    const float* dc1b = (const float*)d_in[11];
    const float* dc2w = (const float*)d_in[12];
    const float* dc2b = (const float*)d_in[13];
    const float* dlw  = (const float*)d_in[14];
    const float* dlb  = (const float*)d_in[15];
    const float* fmw  = (const float*)d_in[16];
    const float* fmb  = (const float*)d_in[17];
    const float* lmw  = (const float*)d_in[18];
    const float* lmb  = (const float*)d_in[19];
    const float* o1w  = (const float*)d_in[20];
    const float* o1b  = (const float*)d_in[21];
    const float* o2w  = (const float*)d_in[22];
    const float* o2b  = (const float*)d_in[23];
    const float* o3w  = (const float*)d_in[24];
    const float* o3b  = (const float*)d_in[25];

    backbone_kernel<<<dim3(NIMG, 2), 256>>>(nodes, depths,
                                            c1w, c1b, c2w, c2b, lw, lb,
                                            dc1w, dc1b, dc2w, dc2b, dlw, dlb);
    head_kernel<<<NB, 192>>>(pos, attmap, fmw, fmb, lmw, lmb,
                             o1w, o1b, o2w, o2b, o3w, o3b,
                             (float*)d_out);
}

// round 2
// speedup vs baseline: 1.0029x; 1.0029x over previous
#include <cuda_runtime.h>

#define NB 32
#define NIMG 640          // 32*5*4 images per backbone
#define CH 50176          // 224*224
#define IMG_SZ 150528     // 3*224*224

// scratch for backbone outputs: [2][640][6]
__device__ float g_backbone[2 * NIMG * 6];

// ---------------------------------------------------------------------------
// Backbone: conv(3->3,3x3,s2) -> maxpool(3,3) -> relu -> conv(3->1,3x3,s2)
//           -> maxpool(3,3) -> relu -> linear 36->6
// One block per (image, backbone). 224x224 streamed in 37 strips of 7 rows.
// ---------------------------------------------------------------------------
__global__ __launch_bounds__(256)
void backbone_kernel(const float* __restrict__ nodes,
                     const float* __restrict__ depths,
                     const float* __restrict__ c1w,  const float* __restrict__ c1b,
                     const float* __restrict__ c2w,  const float* __restrict__ c2b,
                     const float* __restrict__ lw,   const float* __restrict__ lb,
                     const float* __restrict__ dc1w, const float* __restrict__ dc1b,
                     const float* __restrict__ dc2w, const float* __restrict__ dc2b,
                     const float* __restrict__ dlw,  const float* __restrict__ dlb)
{
    const int img = blockIdx.x;   // 0..639
    const int bb  = blockIdx.y;   // 0 = rgb, 1 = depth
    const int tid = threadIdx.x;

    const float* in  = (bb == 0 ? nodes : depths) + (size_t)img * IMG_SZ;
    const float* w1  = bb == 0 ? c1w : dc1w;
    const float* b1  = bb == 0 ? c1b : dc1b;
    const float* w2  = bb == 0 ? c2w : dc2w;
    const float* b2  = bb == 0 ? c2b : dc2b;
    const float* lwp = bb == 0 ? lw  : dlw;
    const float* lbp = bb == 0 ? lb  : dlb;

    __shared__ float s_in[3][7][224];       // current input strip
    __shared__ float s_conv[3][3][112];     // conv1 rows (3 oc x 3 rows x 111)
    __shared__ float s_pool1[3][37][37];    // relu(pool1) result (stage-2 input)
    __shared__ float s_conv2[18][18];
    __shared__ float s_pool2[36];
    __shared__ float s_w1[81];
    __shared__ float s_b1[3];
    __shared__ float s_w2[27];
    __shared__ float s_b2[1];
    __shared__ float s_lw[216];
    __shared__ float s_lb[6];

    if (tid < 81)  s_w1[tid] = w1[tid];
    if (tid < 3)   s_b1[tid] = b1[tid];
    if (tid < 27)  s_w2[tid] = w2[tid];
    if (tid == 0)  s_b2[0]   = b2[0];
    if (tid < 216) s_lw[tid] = lwp[tid];
    if (tid < 6)   s_lb[tid] = lbp[tid];

    // ---- stage 1: 37 strips -------------------------------------------------
    for (int pr = 0; pr < 37; pr++) {
        // load input rows [6*pr, 6*pr+7) for all 3 channels, float4 coalesced
        const float* src = in + 6 * pr * 224;
        for (int q = tid; q < 3 * 7 * 56; q += 256) {
            int c  = q / 392;          // 7*56
            int rr = (q / 56) % 7;
            int x4 = q % 56;
            float4 v = *reinterpret_cast<const float4*>(src + c * CH + rr * 224 + x4 * 4);
            *reinterpret_cast<float4*>(&s_in[c][rr][x4 * 4]) = v;
        }
        __syncthreads();   // S1: s_in ready; also orders pool(prev) before conv

        // conv1: 3 oc x 111 cols, each thread-task computes 3 conv rows
        for (int t2 = tid; t2 < 333; t2 += 256) {
            int oc = t2 / 111;
            int x  = t2 % 111;
            float a0 = 0.f, a1 = 0.f, a2 = 0.f;
            #pragma unroll
            for (int ic = 0; ic < 3; ic++) {
                #pragma unroll
                for (int ky = 0; ky < 3; ky++) {
                    #pragma unroll
                    for (int kx = 0; kx < 3; kx++) {
                        float w = s_w1[(oc * 3 + ic) * 9 + ky * 3 + kx];
                        a0 += w * s_in[ic][ky    ][2 * x + kx];
                        a1 += w * s_in[ic][ky + 2][2 * x + kx];
                        a2 += w * s_in[ic][ky + 4][2 * x + kx];
                    }
                }
            }
            s_conv[oc][0][x] = a0;
            s_conv[oc][1][x] = a1;
            s_conv[oc][2][x] = a2;
        }
        __syncthreads();   // S2: s_conv ready; also orders conv before next load

        // pool1 + bias + relu: 3 oc x 37 cols
        if (tid < 111) {
            int oc = tid / 37, px = tid % 37;
            float m = -1e30f;
            #pragma unroll
            for (int j = 0; j < 3; j++)
                #pragma unroll
                for (int i = 0; i < 3; i++)
                    m = fmaxf(m, s_conv[oc][j][3 * px + i]);
            s_pool1[oc][pr][px] = fmaxf(m + s_b1[oc], 0.f);
        }
    }
    __syncthreads();

    // ---- stage 2: conv2 (18x18) ---------------------------------------------
    for (int t2 = tid; t2 < 324; t2 += 256) {
        int cy = t2 / 18, cx = t2 % 18;
        float acc = 0.f;
        #pragma unroll
        for (int ic = 0; ic < 3; ic++)
            #pragma unroll
            for (int ky = 0; ky < 3; ky++)
                #pragma unroll
                for (int kx = 0; kx < 3; kx++)
                    acc += s_w2[(ic * 3 + ky) * 3 + kx] *
                           s_pool1[ic][2 * cy + ky][2 * cx + kx];
        s_conv2[cy][cx] = acc;
    }
    __syncthreads();

    // pool2 + bias + relu -> 36 features
    if (tid < 36) {
        int py = tid / 6, px = tid % 6;
        float m = -1e30f;
        #pragma unroll
        for (int i = 0; i < 3; i++)
            #pragma unroll
            for (int j = 0; j < 3; j++)
                m = fmaxf(m, s_conv2[3 * py + i][3 * px + j]);
        s_pool2[tid] = fmaxf(m + s_b2[0], 0.f);
    }
    __syncthreads();

    // linear 36 -> 6
    if (tid < 6) {
        float acc = s_lb[tid];
        #pragma unroll
        for (int i = 0; i < 36; i++)
            acc += s_pool2[i] * s_lw[i * 6 + tid];
        g_backbone[bb * (NIMG * 6) + img * 6 + tid] = acc;
    }
}

// ---------------------------------------------------------------------------
// Head: message passing + concat + MLP 360->180->60->6. One block per sample.
// ---------------------------------------------------------------------------
__global__ __launch_bounds__(192)
void head_kernel(const float* __restrict__ pos,  const float* __restrict__ attmap,
                 const float* __restrict__ fmw,  const float* __restrict__ fmb,
                 const float* __restrict__ lmw,  const float* __restrict__ lmb,
                 const float* __restrict__ o1w,  const float* __restrict__ o1b,
                 const float* __restrict__ o2w,  const float* __restrict__ o2b,
                 const float* __restrict__ o3w,  const float* __restrict__ o3b,
                 float* __restrict__ out)
{
    const int b = blockIdx.x;
    const int t = threadIdx.x;

    __shared__ float feat[360];
    __shared__ float h1[180];
    __shared__ float h2[60];
    __shared__ float s_fmw[36], s_fmb[6], s_lmw[36], s_lmb[6];

    if (t < 36) { s_fmw[t] = fmw[t]; s_lmw[t] = lmw[t]; }
    if (t < 6)  { s_fmb[t] = fmb[t]; s_lmb[t] = lmb[t]; }

    // copy backbone features into concat layout [f*4+m][18] = {nf, df, pos_up}
    if (t < 120) {
        int f = t / 24, m = (t % 24) / 6, d = t % 6;
        int fm = f * 4 + m;
        int gi = ((b * 5 + f) * 4 + m) * 6 + d;
        feat[fm * 18 + d]     = g_backbone[gi];
        feat[fm * 18 + 6 + d] = g_backbone[NIMG * 6 + gi];
    }
    __syncthreads();

    // pos_up[b,f,n,d] = sum_m att[b,f,m,n]*(pos[b,f,m]@fmw + fmb)[d]
    //                 + (f>=1 ? (pos[b,f-1,n]@lmw + lmb)[d] : 0)
    if (t < 120) {
        int f = t / 24, n = (t % 24) / 6, d = t % 6;
        const float* pb = pos    + b * 120;  // [5][4][6]
        const float* ab = attmap + b * 80;   // [5][4][4]
        float acc = 0.f;
        #pragma unroll
        for (int m = 0; m < 4; m++) {
            float pm = s_fmb[d];
            #pragma unroll
            for (int e = 0; e < 6; e++)
                pm += pb[f * 24 + m * 6 + e] * s_fmw[e * 6 + d];
            acc += ab[f * 16 + m * 4 + n] * pm;
        }
        if (f >= 1) {
            float pv = s_lmb[d];
            #pragma unroll
            for (int e = 0; e < 6; e++)
                pv += pb[(f - 1) * 24 + n * 6 + e] * s_lmw[e * 6 + d];
            acc += pv;
        }
        feat[(f * 4 + n) * 18 + 12 + d] = acc;
    }
    __syncthreads();

    if (t < 180) {
        float a = o1b[t];
        for (int i = 0; i < 360; i++) a += feat[i] * o1w[i * 180 + t];
        h1[t] = fmaxf(a, 0.f);
    }
    __syncthreads();

    if (t < 60) {
        float a = o2b[t];
        for (int i = 0; i < 180; i++) a += h1[i] * o2w[i * 60 + t];
        h2[t] = fmaxf(a, 0.f);
    }
    __syncthreads();

    if (t < 6) {
        float a = o3b[t];
        for (int i = 0; i < 60; i++) a += h2[i] * o3w[i * 6 + t];
        out[b * 6 + t] = a;
    }
}

extern "C" void kernel_launch(void* const* d_in, const int* in_sizes, int n_in,
                              void* d_out, int out_size)
{
    const float* nodes  = (const float*)d_in[0];
    const float* pos    = (const float*)d_in[1];
    const float* attmap = (const float*)d_in[2];
    const float* depths = (const float*)d_in[3];
    const float* c1w  = (const float*)d_in[4];
    const float* c1b  = (const float*)d_in[5];
    const float* c2w  = (const float*)d_in[6];
    const float* c2b  = (const float*)d_in[7];
    const float* lw   = (const float*)d_in[8];
    const float* lb   = (const float*)d_in[9];
    const float* dc1w = (const float*)d_in[10];
    const float* dc1b = (const float*)d_in[11];
    const float* dc2w = (const float*)d_in[12];
    const float* dc2b = (const float*)d_in[13];
    const float* dlw  = (const float*)d_in[14];
    const float* dlb  = (const float*)d_in[15];
    const float* fmw  = (const float*)d_in[16];
    const float* fmb  = (const float*)d_in[17];
    const float* lmw  = (const float*)d_in[18];
    const float* lmb  = (const float*)d_in[19];
    const float* o1w  = (const float*)d_in[20];
    const float* o1b  = (const float*)d_in[21];
    const float* o2w  = (const float*)d_in[22];
    const float* o2b  = (const float*)d_in[23];
    const float* o3w  = (const float*)d_in[24];
    const float* o3b  = (const float*)d_in[25];

    backbone_kernel<<<dim3(NIMG, 2), 256>>>(nodes, depths,
                                            c1w, c1b, c2w, c2b, lw, lb,
                                            dc1w, dc1b, dc2w, dc2b, dlw, dlb);
    head_kernel<<<NB, 192>>>(pos, attmap, fmw, fmb, lmw, lmb,
                             o1w, o1b, o2w, o2b, o3w, o3b,
                             (float*)d_out);
}

// round 3
// speedup vs baseline: 1.1532x; 1.1498x over previous
#include <cuda_runtime.h>
#include <cstdint>

#define NB 32
#define NIMG 640
#define CH 50176
#define IMG_SZ 150528

__device__ float g_backbone[2 * NIMG * 6];

// dynamic smem layout (floats)
#define O_BUF    0        // 2 x 4704 strip buffers
#define O_CONV   9408     // 1008: conv1 rows [3oc][3j][112]; reused in stage2
#define O_POOL1  10416    // 4107: [3][37][37]
#define O_W2     14523
#define O_B1     14550
#define O_B2     14553
#define O_LW     14554
#define O_LB     14770
#define SMEM_FLOATS 14776
#define SMEM_BYTES  (SMEM_FLOATS * 4)

__device__ __forceinline__ uint32_t s2u(const void* p) {
    uint32_t a;
    asm("{ .reg .u64 t; cvta.to.shared.u64 t, %1; cvt.u32.u64 %0, t; }" : "=r"(a) : "l"(p));
    return a;
}
__device__ __forceinline__ void cp16(uint32_t dst, const float* src) {
    asm volatile("cp.async.cg.shared.global [%0], [%1], 16;" :: "r"(dst), "l"(src));
}
__device__ __forceinline__ void cp_commit() {
    asm volatile("cp.async.commit_group;" ::: "memory");
}
__device__ __forceinline__ void cp_wait1() {
    asm volatile("cp.async.wait_group 1;" ::: "memory");
}

// issue one 7-row x 3-channel strip load (1176 float4 ops across 128 threads)
__device__ __forceinline__ void load_strip(float* sm, int buf, const float* src, int tid) {
    uint32_t dst = s2u(sm + O_BUF + buf * 4704);
    for (int q = tid; q < 1176; q += 128) {
        int c  = q / 392;            // 7*56
        int rr = (q / 56) % 7;
        int x4 = q % 56;
        cp16(dst + (uint32_t)(c * 1568 + rr * 224 + x4 * 4) * 4,
             src + c * CH + rr * 224 + x4 * 4);
    }
    cp_commit();
}

__global__ __launch_bounds__(128)
void backbone_kernel(const float* __restrict__ nodes,
                     const float* __restrict__ depths,
                     const float* __restrict__ c1w,  const float* __restrict__ c1b,
                     const float* __restrict__ c2w,  const float* __restrict__ c2b,
                     const float* __restrict__ lw,   const float* __restrict__ lb,
                     const float* __restrict__ dc1w, const float* __restrict__ dc1b,
                     const float* __restrict__ dc2w, const float* __restrict__ dc2b,
                     const float* __restrict__ dlw,  const float* __restrict__ dlb)
{
    extern __shared__ float sm[];
    const int img = blockIdx.x;
    const int bb  = blockIdx.y;
    const int tid = threadIdx.x;

    const float* in  = (bb == 0 ? nodes : depths) + (size_t)img * IMG_SZ;
    const float* w1  = bb == 0 ? c1w : dc1w;
    const float* b1  = bb == 0 ? c1b : dc1b;
    const float* w2  = bb == 0 ? c2w : dc2w;
    const float* b2  = bb == 0 ? c2b : dc2b;
    const float* lwp = bb == 0 ? lw  : dlw;
    const float* lbp = bb == 0 ? lb  : dlb;

    // conv1 weights -> registers (uniform loads, broadcast in L1)
    float W[81];
    #pragma unroll
    for (int i = 0; i < 81; i++) W[i] = __ldg(w1 + i);

    if (tid < 27) sm[O_W2 + tid] = w2[tid];
    if (tid < 3)  sm[O_B1 + tid] = b1[tid];
    if (tid == 0) sm[O_B2] = b2[0];
    for (int t = tid; t < 216; t += 128) sm[O_LW + t] = lwp[t];
    if (tid < 6)  sm[O_LB + tid] = lbp[tid];

    // prologue: prefetch strips 0 and 1
    load_strip(sm, 0, in, tid);
    load_strip(sm, 1, in + 6 * 224, tid);

    for (int pr = 0; pr < 37; pr++) {
        const int b = pr & 1;
        cp_wait1();            // strip pr complete
        __syncthreads();       // + orders pool(prev) reads before conv writes

        // ---- conv1: 111 columns x 3 conv rows x 3 oc ----------------------
        if (tid < 111) {
            const int x = tid;
            float a[3][3] = {{0.f,0.f,0.f},{0.f,0.f,0.f},{0.f,0.f,0.f}};
            #pragma unroll
            for (int ic = 0; ic < 3; ic++) {
                const float* rp = sm + O_BUF + b * 4704 + ic * 1568 + 2 * x;
                #pragma unroll
                for (int r = 0; r < 7; r++) {
                    float2 p = *reinterpret_cast<const float2*>(rp + r * 224);
                    float  q = rp[r * 224 + 2];
                    #pragma unroll
                    for (int j = 0; j < 3; j++) {
                        const int ky = r - 2 * j;
                        if (ky >= 0 && ky < 3) {
                            #pragma unroll
                            for (int oc = 0; oc < 3; oc++) {
                                const int wb = (oc * 3 + ic) * 9 + ky * 3;
                                a[j][oc] = fmaf(p.x, W[wb],
                                           fmaf(p.y, W[wb + 1],
                                           fmaf(q,   W[wb + 2], a[j][oc])));
                            }
                        }
                    }
                }
            }
            #pragma unroll
            for (int j = 0; j < 3; j++)
                #pragma unroll
                for (int oc = 0; oc < 3; oc++)
                    sm[O_CONV + (oc * 3 + j) * 112 + x] = a[j][oc];
        }
        __syncthreads();       // conv reads of buf[b] done -> safe to refill

        // refill buf[b] with strip pr+2 (or commit empty group to keep count)
        if (pr + 2 < 37) load_strip(sm, b, in + 6 * (pr + 2) * 224, tid);
        else             cp_commit();

        // ---- pool1 + bias + relu -----------------------------------------
        if (tid < 111) {
            const int oc = tid / 37, px = tid % 37;
            float m = -1e30f;
            #pragma unroll
            for (int j = 0; j < 3; j++)
                #pragma unroll
                for (int i = 0; i < 3; i++)
                    m = fmaxf(m, sm[O_CONV + (oc * 3 + j) * 112 + 3 * px + i]);
            sm[O_POOL1 + (oc * 37 + pr) * 37 + px] = fmaxf(m + sm[O_B1 + oc], 0.f);
        }
        // no trailing sync: next-iter top syncthreads orders pool before conv
    }
    __syncthreads();

    // ---- stage 2: conv2 -> pool2 -> relu -> linear 36->6 -------------------
    for (int t2 = tid; t2 < 324; t2 += 128) {
        int cy = t2 / 18, cx = t2 % 18;
        float acc = 0.f;
        #pragma unroll
        for (int ic = 0; ic < 3; ic++)
            #pragma unroll
            for (int ky = 0; ky < 3; ky++)
                #pragma unroll
                for (int kx = 0; kx < 3; kx++)
                    acc = fmaf(sm[O_W2 + (ic * 3 + ky) * 3 + kx],
                               sm[O_POOL1 + (ic * 37 + 2 * cy + ky) * 37 + 2 * cx + kx],
                               acc);
        sm[O_CONV + t2] = acc;
    }
    __syncthreads();

    if (tid < 36) {
        int py = tid / 6, px = tid % 6;
        float m = -1e30f;
        #pragma unroll
        for (int i = 0; i < 3; i++)
            #pragma unroll
            for (int j = 0; j < 3; j++)
                m = fmaxf(m, sm[O_CONV + (3 * py + i) * 18 + 3 * px + j]);
        sm[O_CONV + 400 + tid] = fmaxf(m + sm[O_B2], 0.f);
    }
    __syncthreads();

    if (tid < 6) {
        float acc = sm[O_LB + tid];
        #pragma unroll
        for (int i = 0; i < 36; i++)
            acc = fmaf(sm[O_CONV + 400 + i], sm[O_LW + i * 6 + tid], acc);
        g_backbone[bb * (NIMG * 6) + img * 6 + tid] = acc;
    }
}

// ---------------------------------------------------------------------------
__global__ __launch_bounds__(384)
void head_kernel(const float* __restrict__ pos,  const float* __restrict__ attmap,
                 const float* __restrict__ fmw,  const float* __restrict__ fmb,
                 const float* __restrict__ lmw,  const float* __restrict__ lmb,
                 const float* __restrict__ o1w,  const float* __restrict__ o1b,
                 const float* __restrict__ o2w,  const float* __restrict__ o2b,
                 const float* __restrict__ o3w,  const float* __restrict__ o3b,
                 float* __restrict__ out)
{
    const int bx = blockIdx.x;
    const int t  = threadIdx.x;

    __shared__ float feat[360];
    __shared__ float h1p[2][180], h1[180];
    __shared__ float h2p[2][60],  h2[60];
    __shared__ float s_fmw[36], s_fmb[6], s_lmw[36], s_lmb[6];

    if (t < 36) { s_fmw[t] = fmw[t]; s_lmw[t] = lmw[t]; }
    if (t < 6)  { s_fmb[t] = fmb[t]; s_lmb[t] = lmb[t]; }

    if (t < 120) {
        int f = t / 24, m = (t % 24) / 6, d = t % 6;
        int fm = f * 4 + m;
        int gi = ((bx * 5 + f) * 4 + m) * 6 + d;
        feat[fm * 18 + d]     = g_backbone[gi];
        feat[fm * 18 + 6 + d] = g_backbone[NIMG * 6 + gi];
    }
    __syncthreads();

    if (t < 120) {
        int f = t / 24, n = (t % 24) / 6, d = t % 6;
        const float* pb = pos    + bx * 120;
        const float* ab = attmap + bx * 80;
        float acc = 0.f;
        #pragma unroll
        for (int m = 0; m < 4; m++) {
            float pm = s_fmb[d];
            #pragma unroll
            for (int e = 0; e < 6; e++)
                pm = fmaf(pb[f * 24 + m * 6 + e], s_fmw[e * 6 + d], pm);
            acc = fmaf(ab[f * 16 + m * 4 + n], pm, acc);
        }
        if (f >= 1) {
            float pv = s_lmb[d];
            #pragma unroll
            for (int e = 0; e < 6; e++)
                pv = fmaf(pb[(f - 1) * 24 + n * 6 + e], s_lmw[e * 6 + d], pv);
            acc += pv;
        }
        feat[(f * 4 + n) * 18 + 12 + d] = acc;
    }
    __syncthreads();

    // layer 1: 360 -> 180, 2-way input split
    if (t < 360) {
        int h = t / 180, o = t % 180;
        const float* wc = o1w + (size_t)(h * 180) * 180 + o;
        float a = 0.f;
        #pragma unroll 6
        for (int i = 0; i < 180; i++)
            a = fmaf(feat[h * 180 + i], wc[(size_t)i * 180], a);
        h1p[h][o] = a;
    }
    __syncthreads();
    if (t < 180) h1[t] = fmaxf(h1p[0][t] + h1p[1][t] + o1b[t], 0.f);
    __syncthreads();

    // layer 2: 180 -> 60, 2-way input split
    if (t < 120) {
        int h = t / 60, o = t % 60;
        const float* wc = o2w + (size_t)(h * 90) * 60 + o;
        float a = 0.f;
        #pragma unroll 6
        for (int i = 0; i < 90; i++)
            a = fmaf(h1[h * 90 + i], wc[(size_t)i * 60], a);
        h2p[h][o] = a;
    }
    __syncthreads();
    if (t < 60) h2[t] = fmaxf(h2p[0][t] + h2p[1][t] + o2b[t], 0.f);
    __syncthreads();

    if (t < 6) {
        float a = o3b[t];
        #pragma unroll 6
        for (int i = 0; i < 60; i++)
            a = fmaf(h2[i], o3w[i * 6 + t], a);
        out[bx * 6 + t] = a;
    }
}

extern "C" void kernel_launch(void* const* d_in, const int* in_sizes, int n_in,
                              void* d_out, int out_size)
{
    const float* nodes  = (const float*)d_in[0];
    const float* pos    = (const float*)d_in[1];
    const float* attmap = (const float*)d_in[2];
    const float* depths = (const float*)d_in[3];
    const float* c1w  = (const float*)d_in[4];
    const float* c1b  = (const float*)d_in[5];
    const float* c2w  = (const float*)d_in[6];
    const float* c2b  = (const float*)d_in[7];
    const float* lw   = (const float*)d_in[8];
    const float* lb   = (const float*)d_in[9];
    const float* dc1w = (const float*)d_in[10];
    const float* dc1b = (const float*)d_in[11];
    const float* dc2w = (const float*)d_in[12];
    const float* dc2b = (const float*)d_in[13];
    const float* dlw  = (const float*)d_in[14];
    const float* dlb  = (const float*)d_in[15];
    const float* fmw  = (const float*)d_in[16];
    const float* fmb  = (const float*)d_in[17];
    const float* lmw  = (const float*)d_in[18];
    const float* lmb  = (const float*)d_in[19];
    const float* o1w  = (const float*)d_in[20];
    const float* o1b  = (const float*)d_in[21];
    const float* o2w  = (const float*)d_in[22];
    const float* o2b  = (const float*)d_in[23];
    const float* o3w  = (const float*)d_in[24];
    const float* o3b  = (const float*)d_in[25];

    cudaFuncSetAttribute(backbone_kernel,
                         cudaFuncAttributeMaxDynamicSharedMemorySize, SMEM_BYTES);

    backbone_kernel<<<dim3(NIMG, 2), 128, SMEM_BYTES>>>(
        nodes, depths, c1w, c1b, c2w, c2b, lw, lb,
        dc1w, dc1b, dc2w, dc2b, dlw, dlb);
    head_kernel<<<NB, 384>>>(pos, attmap, fmw, fmb, lmw, lmb,
                             o1w, o1b, o2w, o2b, o3w, o3b,
                             (float*)d_out);
}

// round 4
// speedup vs baseline: 2.9586x; 2.5656x over previous
#include <cuda_runtime.h>
#include <cstdint>

#define NB 32
#define NIMG 640
#define CH 50176
#define IMG_SZ 150528

__device__ float g_backbone[2 * NIMG * 6];

// dynamic smem layout (floats)
#define O_BUF    0        // 2 x 4704 strip buffers (18816 B each)
#define O_CONV   9408     // 1008: conv1 rows [3oc][3j][112]; reused in stage2
#define O_POOL1  10416    // 4107: [3][37][37]
#define O_W2     14524
#define O_B1     14552
#define O_B2     14555
#define O_LW     14556
#define O_LB     14772
#define O_MBAR   14780    // 2 x u64 mbarriers (8B-aligned: 14780*4 = 59120)
#define SMEM_FLOATS 14784
#define SMEM_BYTES  (SMEM_FLOATS * 4)

#define STRIP_BYTES 18816   // 3 * 7 * 224 * 4

__device__ __forceinline__ uint32_t s2u(const void* p) {
    uint32_t a;
    asm("{ .reg .u64 t; cvta.to.shared.u64 t, %1; cvt.u32.u64 %0, t; }" : "=r"(a) : "l"(p));
    return a;
}
__device__ __forceinline__ void mbar_init(uint32_t a, uint32_t cnt) {
    asm volatile("mbarrier.init.shared.b64 [%0], %1;" :: "r"(a), "r"(cnt) : "memory");
}
__device__ __forceinline__ void mbar_expect(uint32_t a, uint32_t tx) {
    asm volatile("mbarrier.arrive.expect_tx.shared.b64 _, [%0], %1;" :: "r"(a), "r"(tx) : "memory");
}
__device__ __forceinline__ void mbar_wait(uint32_t a, uint32_t par) {
    asm volatile(
        "{\n\t.reg .pred P;\n"
        "WL%=:\n\t"
        "mbarrier.try_wait.parity.acquire.cta.shared::cta.b64 P, [%0], %1, 0x989680;\n\t"
        "@!P bra WL%=;\n\t}"
        :: "r"(a), "r"(par) : "memory");
}
__device__ __forceinline__ void bulk_g2s(uint32_t dst, const float* src,
                                         uint32_t bytes, uint32_t mbar) {
    asm volatile(
        "cp.async.bulk.shared::cluster.global.mbarrier::complete_tx::bytes "
        "[%0], [%1], %2, [%3];"
        :: "r"(dst), "l"(src), "r"(bytes), "r"(mbar) : "memory");
}

// one strip = 7 rows x 224 x 3 channels: 3 bulk copies of 6272 B
__device__ __forceinline__ void issue_strip(uint32_t bufb, int buf, const float* src,
                                            uint32_t mbar) {
    mbar_expect(mbar, STRIP_BYTES);
    uint32_t dst = bufb + (uint32_t)buf * STRIP_BYTES;
    #pragma unroll
    for (int ic = 0; ic < 3; ic++)
        bulk_g2s(dst + ic * 6272, src + ic * CH, 6272, mbar);
}

__global__ __launch_bounds__(128)
void backbone_kernel(const float* __restrict__ nodes,
                     const float* __restrict__ depths,
                     const float* __restrict__ c1w,  const float* __restrict__ c1b,
                     const float* __restrict__ c2w,  const float* __restrict__ c2b,
                     const float* __restrict__ lw,   const float* __restrict__ lb,
                     const float* __restrict__ dc1w, const float* __restrict__ dc1b,
                     const float* __restrict__ dc2w, const float* __restrict__ dc2b,
                     const float* __restrict__ dlw,  const float* __restrict__ dlb)
{
    extern __shared__ float sm[];
    const int img = blockIdx.x;
    const int bb  = blockIdx.y;
    const int tid = threadIdx.x;

    const float* in  = (bb == 0 ? nodes : depths) + (size_t)img * IMG_SZ;
    const float* w1  = bb == 0 ? c1w : dc1w;
    const float* b1  = bb == 0 ? c1b : dc1b;
    const float* w2  = bb == 0 ? c2w : dc2w;
    const float* b2  = bb == 0 ? c2b : dc2b;
    const float* lwp = bb == 0 ? lw  : dlw;
    const float* lbp = bb == 0 ? lb  : dlb;

    const uint32_t bufb = s2u(sm + O_BUF);
    const uint32_t mb0  = s2u(sm + O_MBAR);
    const uint32_t mb1  = mb0 + 8;

    // conv1 weights -> registers (uniform loads, broadcast)
    float W[81];
    #pragma unroll
    for (int i = 0; i < 81; i++) W[i] = __ldg(w1 + i);

    if (tid < 27) sm[O_W2 + tid] = w2[tid];
    if (tid < 3)  sm[O_B1 + tid] = b1[tid];
    if (tid == 0) sm[O_B2] = b2[0];
    for (int t = tid; t < 216; t += 128) sm[O_LW + t] = lwp[t];
    if (tid < 6)  sm[O_LB + tid] = lbp[tid];

    if (tid == 0) {
        mbar_init(mb0, 1);
        mbar_init(mb1, 1);
        asm volatile("fence.proxy.async.shared::cta;" ::: "memory");
    }
    __syncthreads();

    // prologue: prefetch strips 0 and 1
    if (tid == 0) {
        issue_strip(bufb, 0, in, mb0);
        issue_strip(bufb, 1, in + 6 * 224, mb1);
    }

    for (int pr = 0; pr < 37; pr++) {
        const int b = pr & 1;
        mbar_wait(b ? mb1 : mb0, (pr >> 1) & 1);   // strip pr landed
        __syncthreads();   // orders pool(prev) s_conv reads before conv writes

        // ---- conv1: 111 columns x 3 conv rows x 3 oc ----------------------
        if (tid < 111) {
            const int x = tid;
            float a[3][3] = {{0.f,0.f,0.f},{0.f,0.f,0.f},{0.f,0.f,0.f}};
            #pragma unroll
            for (int ic = 0; ic < 3; ic++) {
                const float* rp = sm + O_BUF + b * 4704 + ic * 1568 + 2 * x;
                #pragma unroll
                for (int r = 0; r < 7; r++) {
                    float2 p = *reinterpret_cast<const float2*>(rp + r * 224);
                    float  q = rp[r * 224 + 2];
                    #pragma unroll
                    for (int j = 0; j < 3; j++) {
                        const int ky = r - 2 * j;
                        if (ky >= 0 && ky < 3) {
                            #pragma unroll
                            for (int oc = 0; oc < 3; oc++) {
                                const int wb = (oc * 3 + ic) * 9 + ky * 3;
                                a[j][oc] = fmaf(p.x, W[wb],
                                           fmaf(p.y, W[wb + 1],
                                           fmaf(q,   W[wb + 2], a[j][oc])));
                            }
                        }
                    }
                }
            }
            #pragma unroll
            for (int j = 0; j < 3; j++)
                #pragma unroll
                for (int oc = 0; oc < 3; oc++)
                    sm[O_CONV + (oc * 3 + j) * 112 + x] = a[j][oc];
        }
        __syncthreads();   // conv reads of buf[b] retired -> safe to refill

        if (tid == 0 && pr + 2 < 37)
            issue_strip(bufb, b, in + 6 * (pr + 2) * 224, b ? mb1 : mb0);

        // ---- pool1 + bias + relu -----------------------------------------
        if (tid < 111) {
            const int oc = tid / 37, px = tid % 37;
            float m = -1e30f;
            #pragma unroll
            for (int j = 0; j < 3; j++)
                #pragma unroll
                for (int i = 0; i < 3; i++)
                    m = fmaxf(m, sm[O_CONV + (oc * 3 + j) * 112 + 3 * px + i]);
            sm[O_POOL1 + (oc * 37 + pr) * 37 + px] = fmaxf(m + sm[O_B1 + oc], 0.f);
        }
        // next-iteration top __syncthreads orders pool writes/reads
    }
    __syncthreads();

    // ---- stage 2: conv2 -> pool2 -> relu -> linear 36->6 -------------------
    for (int t2 = tid; t2 < 324; t2 += 128) {
        int cy = t2 / 18, cx = t2 % 18;
        float acc = 0.f;
        #pragma unroll
        for (int ic = 0; ic < 3; ic++)
            #pragma unroll
            for (int ky = 0; ky < 3; ky++)
                #pragma unroll
                for (int kx = 0; kx < 3; kx++)
                    acc = fmaf(sm[O_W2 + (ic * 3 + ky) * 3 + kx],
                               sm[O_POOL1 + (ic * 37 + 2 * cy + ky) * 37 + 2 * cx + kx],
                               acc);
        sm[O_CONV + t2] = acc;
    }
    __syncthreads();

    if (tid < 36) {
        int py = tid / 6, px = tid % 6;
        float m = -1e30f;
        #pragma unroll
        for (int i = 0; i < 3; i++)
            #pragma unroll
            for (int j = 0; j < 3; j++)
                m = fmaxf(m, sm[O_CONV + (3 * py + i) * 18 + 3 * px + j]);
        sm[O_CONV + 400 + tid] = fmaxf(m + sm[O_B2], 0.f);
    }
    __syncthreads();

    if (tid < 6) {
        float acc = sm[O_LB + tid];
        #pragma unroll
        for (int i = 0; i < 36; i++)
            acc = fmaf(sm[O_CONV + 400 + i], sm[O_LW + i * 6 + tid], acc);
        g_backbone[bb * (NIMG * 6) + img * 6 + tid] = acc;
    }
}

// ---------------------------------------------------------------------------
// Head: pure 32-bit indexing, 2-way split on layer 1/2, 384 threads.
// ---------------------------------------------------------------------------
__global__ __launch_bounds__(384)
void head_kernel(const float* __restrict__ pos,  const float* __restrict__ attmap,
                 const float* __restrict__ fmw,  const float* __restrict__ fmb,
                 const float* __restrict__ lmw,  const float* __restrict__ lmb,
                 const float* __restrict__ o1w,  const float* __restrict__ o1b,
                 const float* __restrict__ o2w,  const float* __restrict__ o2b,
                 const float* __restrict__ o3w,  const float* __restrict__ o3b,
                 float* __restrict__ out)
{
    const int bx = blockIdx.x;
    const int t  = threadIdx.x;

    __shared__ float feat[360];
    __shared__ float h1p[2][180], h1[180];
    __shared__ float h2p[2][60],  h2[60];
    __shared__ float s_fmw[36], s_fmb[6], s_lmw[36], s_lmb[6];

    if (t < 36) { s_fmw[t] = fmw[t]; s_lmw[t] = lmw[t]; }
    if (t < 6)  { s_fmb[t] = fmb[t]; s_lmb[t] = lmb[t]; }

    if (t < 120) {
        int f = t / 24, m = (t % 24) / 6, d = t % 6;
        int fm = f * 4 + m;
        int gi = ((bx * 5 + f) * 4 + m) * 6 + d;
        feat[fm * 18 + d]     = g_backbone[gi];
        feat[fm * 18 + 6 + d] = g_backbone[NIMG * 6 + gi];
    }
    __syncthreads();

    if (t < 120) {
        int f = t / 24, n = (t % 24) / 6, d = t % 6;
        const float* pb = pos    + bx * 120;
        const float* ab = attmap + bx * 80;
        float acc = 0.f;
        #pragma unroll
        for (int m = 0; m < 4; m++) {
            float pm = s_fmb[d];
            #pragma unroll
            for (int e = 0; e < 6; e++)
                pm = fmaf(pb[f * 24 + m * 6 + e], s_fmw[e * 6 + d], pm);
            acc = fmaf(ab[f * 16 + m * 4 + n], pm, acc);
        }
        if (f >= 1) {
            float pv = s_lmb[d];
            #pragma unroll
            for (int e = 0; e < 6; e++)
                pv = fmaf(pb[(f - 1) * 24 + n * 6 + e], s_lmw[e * 6 + d], pv);
            acc += pv;
        }
        feat[(f * 4 + n) * 18 + 12 + d] = acc;
    }
    __syncthreads();

    // layer 1: 360 -> 180, 2-way input split, 32-bit indexing
    if (t < 360) {
        int h = (t >= 180) ? 1 : 0;
        int o = t - h * 180;
        int base = h * 180;
        float a = 0.f;
        #pragma unroll 10
        for (int i = 0; i < 180; i++)
            a = fmaf(feat[base + i], __ldg(o1w + (base + i) * 180 + o), a);
        h1p[h][o] = a;
    }
    __syncthreads();
    if (t < 180) h1[t] = fmaxf(h1p[0][t] + h1p[1][t] + o1b[t], 0.f);
    __syncthreads();

    // layer 2: 180 -> 60, 2-way input split
    if (t < 120) {
        int h = (t >= 60) ? 1 : 0;
        int o = t - h * 60;
        int base = h * 90;
        float a = 0.f;
        #pragma unroll 10
        for (int i = 0; i < 90; i++)
            a = fmaf(h1[base + i], __ldg(o2w + (base + i) * 60 + o), a);
        h2p[h][o] = a;
    }
    __syncthreads();
    if (t < 60) h2[t] = fmaxf(h2p[0][t] + h2p[1][t] + o2b[t], 0.f);
    __syncthreads();

    if (t < 6) {
        float a = o3b[t];
        #pragma unroll 10
        for (int i = 0; i < 60; i++)
            a = fmaf(h2[i], __ldg(o3w + i * 6 + t), a);
        out[bx * 6 + t] = a;
    }
}

extern "C" void kernel_launch(void* const* d_in, const int* in_sizes, int n_in,
                              void* d_out, int out_size)
{
    const float* nodes  = (const float*)d_in[0];
    const float* pos    = (const float*)d_in[1];
    const float* attmap = (const float*)d_in[2];
    const float* depths = (const float*)d_in[3];
    const float* c1w  = (const float*)d_in[4];
    const float* c1b  = (const float*)d_in[5];
    const float* c2w  = (const float*)d_in[6];
    const float* c2b  = (const float*)d_in[7];
    const float* lw   = (const float*)d_in[8];
    const float* lb   = (const float*)d_in[9];
    const float* dc1w = (const float*)d_in[10];
    const float* dc1b = (const float*)d_in[11];
    const float* dc2w = (const float*)d_in[12];
    const float* dc2b = (const float*)d_in[13];
    const float* dlw  = (const float*)d_in[14];
    const float* dlb  = (const float*)d_in[15];
    const float* fmw  = (const float*)d_in[16];
    const float* fmb  = (const float*)d_in[17];
    const float* lmw  = (const float*)d_in[18];
    const float* lmb  = (const float*)d_in[19];
    const float* o1w  = (const float*)d_in[20];
    const float* o1b  = (const float*)d_in[21];
    const float* o2w  = (const float*)d_in[22];
    const float* o2b  = (const float*)d_in[23];
    const float* o3w  = (const float*)d_in[24];
    const float* o3b  = (const float*)d_in[25];

    cudaFuncSetAttribute(backbone_kernel,
                         cudaFuncAttributeMaxDynamicSharedMemorySize, SMEM_BYTES);

    backbone_kernel<<<dim3(NIMG, 2), 128, SMEM_BYTES>>>(
        nodes, depths, c1w, c1b, c2w, c2b, lw, lb,
        dc1w, dc1b, dc2w, dc2b, dlw, dlb);
    head_kernel<<<NB, 384>>>(pos, attmap, fmw, fmb, lmw, lmb,
                             o1w, o1b, o2w, o2b, o3w, o3b,
                             (float*)d_out);
}

// round 5
// speedup vs baseline: 3.1853x; 1.0766x over previous
#include <cuda_runtime.h>
#include <cstdint>

#define NB 32
#define NIMG 640
#define CH 50176
#define IMG_SZ 150528

__device__ float g_backbone[2 * NIMG * 6];

// dynamic smem layout (floats)
#define O_BUF    0        // 2 x 4704 strip buffers (18816 B each)
#define O_CONV   9408     // 1008: conv1 rows [3oc][3j][112]; reused in stage2
#define O_POOL1  10416    // 4107: [3][37][37]
#define O_W2     14524
#define O_B1     14552
#define O_B2     14555
#define O_LW     14556
#define O_LB     14772
#define O_MBAR   14780    // 2 x u64 mbarriers (8B aligned)
#define SMEM_FLOATS 14784
#define SMEM_BYTES  (SMEM_FLOATS * 4)

#define STRIP_BYTES 18816   // 3 * 7 * 224 * 4

__device__ __forceinline__ uint32_t s2u(const void* p) {
    uint32_t a;
    asm("{ .reg .u64 t; cvta.to.shared.u64 t, %1; cvt.u32.u64 %0, t; }" : "=r"(a) : "l"(p));
    return a;
}
__device__ __forceinline__ void mbar_init(uint32_t a, uint32_t cnt) {
    asm volatile("mbarrier.init.shared.b64 [%0], %1;" :: "r"(a), "r"(cnt) : "memory");
}
__device__ __forceinline__ void mbar_expect(uint32_t a, uint32_t tx) {
    asm volatile("mbarrier.arrive.expect_tx.shared.b64 _, [%0], %1;" :: "r"(a), "r"(tx) : "memory");
}
__device__ __forceinline__ void mbar_wait(uint32_t a, uint32_t par) {
    asm volatile(
        "{\n\t.reg .pred P;\n"
        "WL%=:\n\t"
        "mbarrier.try_wait.parity.acquire.cta.shared::cta.b64 P, [%0], %1, 0x989680;\n\t"
        "@!P bra WL%=;\n\t}"
        :: "r"(a), "r"(par) : "memory");
}
__device__ __forceinline__ void bulk_g2s(uint32_t dst, const float* src,
                                         uint32_t bytes, uint32_t mbar) {
    asm volatile(
        "cp.async.bulk.shared::cluster.global.mbarrier::complete_tx::bytes "
        "[%0], [%1], %2, [%3];"
        :: "r"(dst), "l"(src), "r"(bytes), "r"(mbar) : "memory");
}
__device__ __forceinline__ void l2_prefetch(const float* p) {
    asm volatile("prefetch.global.L2 [%0];" :: "l"(p));
}

__device__ __forceinline__ void issue_strip(uint32_t bufb, int buf, const float* src,
                                            uint32_t mbar) {
    mbar_expect(mbar, STRIP_BYTES);
    uint32_t dst = bufb + (uint32_t)buf * STRIP_BYTES;
    #pragma unroll
    for (int ic = 0; ic < 3; ic++)
        bulk_g2s(dst + ic * 6272, src + ic * CH, 6272, mbar);
}

__global__ __launch_bounds__(128)
void backbone_kernel(const float* __restrict__ nodes,
                     const float* __restrict__ depths,
                     const float* __restrict__ c1w,  const float* __restrict__ c1b,
                     const float* __restrict__ c2w,  const float* __restrict__ c2b,
                     const float* __restrict__ lw,   const float* __restrict__ lb,
                     const float* __restrict__ dc1w, const float* __restrict__ dc1b,
                     const float* __restrict__ dc2w, const float* __restrict__ dc2b,
                     const float* __restrict__ dlw,  const float* __restrict__ dlb)
{
    extern __shared__ float sm[];
    const int img = blockIdx.x;
    const int bb  = blockIdx.y;
    const int tid = threadIdx.x;

    const float* in  = (bb == 0 ? nodes : depths) + (size_t)img * IMG_SZ;
    const float* w1  = bb == 0 ? c1w : dc1w;
    const float* b1  = bb == 0 ? c1b : dc1b;
    const float* w2  = bb == 0 ? c2w : dc2w;
    const float* b2  = bb == 0 ? c2b : dc2b;
    const float* lwp = bb == 0 ? lw  : dlw;
    const float* lbp = bb == 0 ? lb  : dlb;

    const uint32_t bufb = s2u(sm + O_BUF);
    const uint32_t mb0  = s2u(sm + O_MBAR);
    const uint32_t mb1  = mb0 + 8;

    float W[81];
    #pragma unroll
    for (int i = 0; i < 81; i++) W[i] = __ldg(w1 + i);

    if (tid < 27) sm[O_W2 + tid] = w2[tid];
    if (tid < 3)  sm[O_B1 + tid] = b1[tid];
    if (tid == 0) sm[O_B2] = b2[0];
    for (int t = tid; t < 216; t += 128) sm[O_LW + t] = lwp[t];
    if (tid < 6)  sm[O_LB + tid] = lbp[tid];

    if (tid == 0) {
        mbar_init(mb0, 1);
        mbar_init(mb1, 1);
        asm volatile("fence.proxy.async.shared::cta;" ::: "memory");
    }
    __syncthreads();

    if (tid == 0) {
        issue_strip(bufb, 0, in, mb0);
        issue_strip(bufb, 1, in + 6 * 224, mb1);
    }

    for (int pr = 0; pr < 37; pr++) {
        const int b = pr & 1;
        mbar_wait(b ? mb1 : mb0, (pr >> 1) & 1);
        __syncthreads();

        if (tid < 111) {
            const int x = tid;
            float a[3][3] = {{0.f,0.f,0.f},{0.f,0.f,0.f},{0.f,0.f,0.f}};
            #pragma unroll
            for (int ic = 0; ic < 3; ic++) {
                const float* rp = sm + O_BUF + b * 4704 + ic * 1568 + 2 * x;
                #pragma unroll
                for (int r = 0; r < 7; r++) {
                    float2 p = *reinterpret_cast<const float2*>(rp + r * 224);
                    float  q = rp[r * 224 + 2];
                    #pragma unroll
                    for (int j = 0; j < 3; j++) {
                        const int ky = r - 2 * j;
                        if (ky >= 0 && ky < 3) {
                            #pragma unroll
                            for (int oc = 0; oc < 3; oc++) {
                                const int wb = (oc * 3 + ic) * 9 + ky * 3;
                                a[j][oc] = fmaf(p.x, W[wb],
                                           fmaf(p.y, W[wb + 1],
                                           fmaf(q,   W[wb + 2], a[j][oc])));
                            }
                        }
                    }
                }
            }
            #pragma unroll
            for (int j = 0; j < 3; j++)
                #pragma unroll
                for (int oc = 0; oc < 3; oc++)
                    sm[O_CONV + (oc * 3 + j) * 112 + x] = a[j][oc];
        }
        __syncthreads();

        if (tid == 0 && pr + 2 < 37)
            issue_strip(bufb, b, in + 6 * (pr + 2) * 224, b ? mb1 : mb0);

        if (tid < 111) {
            const int oc = tid / 37, px = tid % 37;
            float m = -1e30f;
            #pragma unroll
            for (int j = 0; j < 3; j++)
                #pragma unroll
                for (int i = 0; i < 3; i++)
                    m = fmaxf(m, sm[O_CONV + (oc * 3 + j) * 112 + 3 * px + i]);
            sm[O_POOL1 + (oc * 37 + pr) * 37 + px] = fmaxf(m + sm[O_B1 + oc], 0.f);
        }
    }
    __syncthreads();

    for (int t2 = tid; t2 < 324; t2 += 128) {
        int cy = t2 / 18, cx = t2 % 18;
        float acc = 0.f;
        #pragma unroll
        for (int ic = 0; ic < 3; ic++)
            #pragma unroll
            for (int ky = 0; ky < 3; ky++)
                #pragma unroll
                for (int kx = 0; kx < 3; kx++)
                    acc = fmaf(sm[O_W2 + (ic * 3 + ky) * 3 + kx],
                               sm[O_POOL1 + (ic * 37 + 2 * cy + ky) * 37 + 2 * cx + kx],
                               acc);
        sm[O_CONV + t2] = acc;
    }
    __syncthreads();

    if (tid < 36) {
        int py = tid / 6, px = tid % 6;
        float m = -1e30f;
        #pragma unroll
        for (int i = 0; i < 3; i++)
            #pragma unroll
            for (int j = 0; j < 3; j++)
                m = fmaxf(m, sm[O_CONV + (3 * py + i) * 18 + 3 * px + j]);
        sm[O_CONV + 400 + tid] = fmaxf(m + sm[O_B2], 0.f);
    }
    __syncthreads();

    if (tid < 6) {
        float acc = sm[O_LB + tid];
        #pragma unroll
        for (int i = 0; i < 36; i++)
            acc = fmaf(sm[O_CONV + 400 + i], sm[O_LW + i * 6 + tid], acc);
        g_backbone[bb * (NIMG * 6) + img * 6 + tid] = acc;
    }
}

// ---------------------------------------------------------------------------
// Head: 768 threads/block, one block per sample.
// - weights prefetched to L2 at entry (data-independent)
// - feat copy + message passing in DISJOINT warps (one barrier phase)
// - layer1/2 with 4-way input split; partials combined in smem
// ---------------------------------------------------------------------------
__global__ __launch_bounds__(768)
void head_kernel(const float* __restrict__ pos,  const float* __restrict__ attmap,
                 const float* __restrict__ fmw,  const float* __restrict__ fmb,
                 const float* __restrict__ lmw,  const float* __restrict__ lmb,
                 const float* __restrict__ o1w,  const float* __restrict__ o1b,
                 const float* __restrict__ o2w,  const float* __restrict__ o2b,
                 const float* __restrict__ o3w,  const float* __restrict__ o3b,
                 float* __restrict__ out)
{
    const int bx = blockIdx.x;
    const int t  = threadIdx.x;

    __shared__ float feat[360];
    __shared__ float h1p[4][180], h1[180];
    __shared__ float h2p[4][60],  h2[60];
    __shared__ float h3p[6][6];

    // L2 prefetch of MLP weights: o1w 64800 f (2025 x 128B), o2w 10800 f (338)
    {
        for (int i = t; i < 2025; i += 768) l2_prefetch(o1w + i * 32);
        for (int i = t; i < 338;  i += 768) l2_prefetch(o2w + i * 32);
        if (t < 12) l2_prefetch(o3w + t * 32);
    }

    // warps 0-3: copy backbone features | warps 12-15: message passing
    if (t < 120) {
        int f = t / 24, m = (t % 24) / 6, d = t % 6;
        int fm = f * 4 + m;
        int gi = ((bx * 5 + f) * 4 + m) * 6 + d;
        feat[fm * 18 + d]     = g_backbone[gi];
        feat[fm * 18 + 6 + d] = g_backbone[NIMG * 6 + gi];
    } else if (t >= 384 && t < 504) {
        int tt = t - 384;
        int f = tt / 24, n = (tt % 24) / 6, d = tt % 6;
        const float* pb = pos    + bx * 120;
        const float* ab = attmap + bx * 80;
        float acc = 0.f;
        #pragma unroll
        for (int m = 0; m < 4; m++) {
            float pm = __ldg(fmb + d);
            #pragma unroll
            for (int e = 0; e < 6; e++)
                pm = fmaf(__ldg(pb + f * 24 + m * 6 + e), __ldg(fmw + e * 6 + d), pm);
            acc = fmaf(__ldg(ab + f * 16 + m * 4 + n), pm, acc);
        }
        if (f >= 1) {
            float pv = __ldg(lmb + d);
            #pragma unroll
            for (int e = 0; e < 6; e++)
                pv = fmaf(__ldg(pb + (f - 1) * 24 + n * 6 + e), __ldg(lmw + e * 6 + d), pv);
            acc += pv;
        }
        feat[(f * 4 + n) * 18 + 12 + d] = acc;
    }
    __syncthreads();

    // layer 1: 360 -> 180, 4-way input split (q in 0..3, 90 inputs each)
    if (t < 720) {
        int q = t / 180, o = t - q * 180;
        int base = q * 90;
        const float* wp = o1w + base * 180 + o;
        float a = 0.f;
        #pragma unroll 15
        for (int i = 0; i < 90; i++)
            a = fmaf(feat[base + i], wp[i * 180], a);
        h1p[q][o] = a;
    }
    __syncthreads();
    if (t < 180)
        h1[t] = fmaxf(h1p[0][t] + h1p[1][t] + h1p[2][t] + h1p[3][t] + o1b[t], 0.f);
    __syncthreads();

    // layer 2: 180 -> 60, 4-way input split (45 inputs each)
    if (t < 240) {
        int q = t / 60, o = t - q * 60;
        int base = q * 45;
        const float* wp = o2w + base * 60 + o;
        float a = 0.f;
        #pragma unroll 15
        for (int i = 0; i < 45; i++)
            a = fmaf(h1[base + i], wp[i * 60], a);
        h2p[q][o] = a;
    }
    __syncthreads();
    if (t < 60)
        h2[t] = fmaxf(h2p[0][t] + h2p[1][t] + h2p[2][t] + h2p[3][t] + o2b[t], 0.f);
    __syncthreads();

    // layer 3: 60 -> 6, 6-way input split (10 inputs each)
    if (t < 36) {
        int q = t / 6, o = t - q * 6;
        int base = q * 10;
        float a = 0.f;
        #pragma unroll
        for (int i = 0; i < 10; i++)
            a = fmaf(h2[base + i], __ldg(o3w + (base + i) * 6 + o), a);
        h3p[q][o] = a;
    }
    __syncthreads();
    if (t < 6) {
        float a = o3b[t];
        #pragma unroll
        for (int q = 0; q < 6; q++) a += h3p[q][t];
        out[bx * 6 + t] = a;
    }
}

extern "C" void kernel_launch(void* const* d_in, const int* in_sizes, int n_in,
                              void* d_out, int out_size)
{
    const float* nodes  = (const float*)d_in[0];
    const float* pos    = (const float*)d_in[1];
    const float* attmap = (const float*)d_in[2];
    const float* depths = (const float*)d_in[3];
    const float* c1w  = (const float*)d_in[4];
    const float* c1b  = (const float*)d_in[5];
    const float* c2w  = (const float*)d_in[6];
    const float* c2b  = (const float*)d_in[7];
    const float* lw   = (const float*)d_in[8];
    const float* lb   = (const float*)d_in[9];
    const float* dc1w = (const float*)d_in[10];
    const float* dc1b = (const float*)d_in[11];
    const float* dc2w = (const float*)d_in[12];
    const float* dc2b = (const float*)d_in[13];
    const float* dlw  = (const float*)d_in[14];
    const float* dlb  = (const float*)d_in[15];
    const float* fmw  = (const float*)d_in[16];
    const float* fmb  = (const float*)d_in[17];
    const float* lmw  = (const float*)d_in[18];
    const float* lmb  = (const float*)d_in[19];
    const float* o1w  = (const float*)d_in[20];
    const float* o1b  = (const float*)d_in[21];
    const float* o2w  = (const float*)d_in[22];
    const float* o2b  = (const float*)d_in[23];
    const float* o3w  = (const float*)d_in[24];
    const float* o3b  = (const float*)d_in[25];

    cudaFuncSetAttribute(backbone_kernel,
                         cudaFuncAttributeMaxDynamicSharedMemorySize, SMEM_BYTES);

    backbone_kernel<<<dim3(NIMG, 2), 128, SMEM_BYTES>>>(
        nodes, depths, c1w, c1b, c2w, c2b, lw, lb,
        dc1w, dc1b, dc2w, dc2b, dlw, dlb);
    head_kernel<<<NB, 768>>>(pos, attmap, fmw, fmb, lmw, lmb,
                             o1w, o1b, o2w, o2b, o3w, o3b,
                             (float*)d_out);
}